// round 11
// baseline (speedup 1.0000x reference)
#include <cuda_runtime.h>
#include <cuda_bf16.h>
#include <math.h>
#include <stdint.h>

// ---------------------------------------------------------------------------
// CrossAttention2D (B=2, C=256, N=4096, heads=8, d=64) — bf16 tensor-core path
// R11: GEMMs widened to k=32 per pipeline stage (3-stage, 1 sync/step),
//      KAUG padded to 352; attention unchanged from R10 (best).
// ---------------------------------------------------------------------------

#define NPIX 4096
#define KAUG 352   // 324 padded to mult of 32

__device__ float g_alpha[2 * NPIX];
__device__ float g_biasC[1536];
__device__ __nv_bfloat16 g_Wb[1536 * KAUG];
__device__ __nv_bfloat16 g_woutb[256 * 512];
__device__ __nv_bfloat16 g_augT[2 * NPIX * KAUG];
__device__ __nv_bfloat16 g_qkvb[48 * NPIX * 64];   // [(b*3+part)*8+h][n][64]
__device__ __nv_bfloat16 g_ob[2 * NPIX * 512];     // [b][n][512]

// ---------------- PTX helpers ----------------
__device__ __forceinline__ void ldsm_x4(uint32_t* r, uint32_t a) {
    asm volatile("ldmatrix.sync.aligned.m8n8.x4.shared.b16 {%0,%1,%2,%3},[%4];"
                 : "=r"(r[0]), "=r"(r[1]), "=r"(r[2]), "=r"(r[3]) : "r"(a));
}
__device__ __forceinline__ void ldsm_x4t(uint32_t* r, uint32_t a) {
    asm volatile("ldmatrix.sync.aligned.m8n8.x4.trans.shared.b16 {%0,%1,%2,%3},[%4];"
                 : "=r"(r[0]), "=r"(r[1]), "=r"(r[2]), "=r"(r[3]) : "r"(a));
}
__device__ __forceinline__ void mma16816(float* c, uint32_t a0, uint32_t a1, uint32_t a2,
                                         uint32_t a3, uint32_t b0, uint32_t b1) {
    asm volatile("mma.sync.aligned.m16n8k16.row.col.f32.bf16.bf16.f32 "
                 "{%0,%1,%2,%3},{%4,%5,%6,%7},{%8,%9},{%0,%1,%2,%3};"
                 : "+f"(c[0]), "+f"(c[1]), "+f"(c[2]), "+f"(c[3])
                 : "r"(a0), "r"(a1), "r"(a2), "r"(a3), "r"(b0), "r"(b1));
}
__device__ __forceinline__ uint32_t pack_bf16(float lo, float hi) {
    uint32_t r; asm("cvt.rn.bf16x2.f32 %0, %1, %2;" : "=r"(r) : "f"(hi), "f"(lo)); return r;
}
__device__ __forceinline__ float ex2(float x) {
    float y; asm("ex2.approx.ftz.f32 %0, %1;" : "=f"(y) : "f"(x)); return y;
}
__device__ __forceinline__ void cp16(uint32_t d, const void* s) {
    asm volatile("cp.async.cg.shared.global [%0], [%1], 16;" :: "r"(d), "l"(s));
}
#define CP_COMMIT asm volatile("cp.async.commit_group;")
template <int N> __device__ __forceinline__ void cp_wait() {
    asm volatile("cp.async.wait_group %0;" :: "n"(N));
}

// ---------------- launch 1: preprocess (minmax,d,sobel,alpha,data cols) ----
__global__ void __launch_bounds__(1024) preprocess_kernel(
    const float* __restrict__ dsm, const float* __restrict__ w_alpha,
    const float* __restrict__ b_alpha) {
    __shared__ float sd[4096], smag[4096], rmin[32], rmax[32];
    __shared__ float s_mn, s_mx;
    const int b = blockIdx.x, t = threadIdx.x;
    float v[4], mn = 1e30f, mx = -1e30f;
#pragma unroll
    for (int i = 0; i < 4; ++i) {
        v[i] = dsm[b * 4096 + t + i * 1024];
        mn = fminf(mn, v[i]); mx = fmaxf(mx, v[i]);
    }
#pragma unroll
    for (int o = 16; o; o >>= 1) {
        mn = fminf(mn, __shfl_xor_sync(~0u, mn, o));
        mx = fmaxf(mx, __shfl_xor_sync(~0u, mx, o));
    }
    if ((t & 31) == 0) { rmin[t >> 5] = mn; rmax[t >> 5] = mx; }
    __syncthreads();
    if (t < 32) {
        mn = rmin[t]; mx = rmax[t];
#pragma unroll
        for (int o = 16; o; o >>= 1) {
            mn = fminf(mn, __shfl_xor_sync(~0u, mn, o));
            mx = fmaxf(mx, __shfl_xor_sync(~0u, mx, o));
        }
        if (t == 0) { s_mn = mn; s_mx = mx; }
    }
    __syncthreads();
    const float inv = 1.f / (s_mx - s_mn + 1e-6f);
#pragma unroll
    for (int i = 0; i < 4; ++i) sd[t + i * 1024] = (v[i] - s_mn) * inv;
    __syncthreads();
#pragma unroll
    for (int i = 0; i < 4; ++i) {
        int p = t + i * 1024, h = p >> 6, w = p & 63;
#define DP(yy, xx) (((unsigned)(yy) > 63u || (unsigned)(xx) > 63u) ? 0.f : sd[(yy) * 64 + (xx)])
        float d00 = DP(h-1,w-1), d01 = DP(h-1,w), d02 = DP(h-1,w+1);
        float d10 = DP(h,w-1),                    d12 = DP(h,w+1);
        float d20 = DP(h+1,w-1), d21 = DP(h+1,w), d22 = DP(h+1,w+1);
#undef DP
        float gx = d00 - d02 + 2.f * (d10 - d12) + d20 - d22;
        float gy = d00 + 2.f * d01 + d02 - d20 - 2.f * d21 - d22;
        float rx = fmaxf(gx, 0.f), ry = fmaxf(gy, 0.f);
        smag[p] = sqrtf(rx * rx + ry * ry + 1e-12f);
        float dv = sd[p];
        __nv_bfloat16* row = g_augT + ((size_t)((b << 12) + p)) * KAUG;
        row[256] = __float2bfloat16(dv); row[321] = __float2bfloat16(dv);
        row[322] = __float2bfloat16(gx); row[323] = __float2bfloat16(gy);
        uint64_t* zp = (uint64_t*)(row + 324);   // cols 324..351 zero (56B, 8B-aligned)
#pragma unroll
        for (int z = 0; z < 7; ++z) zp[z] = 0ull;
    }
    __syncthreads();
#pragma unroll
    for (int i = 0; i < 4; ++i) {
        int p = t + i * 1024, h = p >> 6, w = p & 63;
        float acc = b_alpha[0];
#pragma unroll
        for (int dy = -1; dy <= 1; ++dy)
#pragma unroll
            for (int dx = -1; dx <= 1; ++dx) {
                int yy = h + dy, xx = w + dx;
                float m = ((unsigned)yy > 63u || (unsigned)xx > 63u) ? 0.f : smag[yy * 64 + xx];
                acc += m * w_alpha[(dy + 1) * 3 + (dx + 1)];
            }
        g_alpha[(b << 12) + p] = 1.f / (1.f + expf(-acc));
    }
}

// ---------------- launch 2: PE (wide — 1024 blocks) ----------------
__global__ void pe_kernel() {
    int idx = blockIdx.x * 256 + threadIdx.x;   // 4096*64
    int p = idx >> 6, q = idx & 63, quad = q >> 4, kk = q & 15;
    float omega = exp2f(-(float)kk * 0.8304820237218406f);
    float coord = (quad < 2) ? (-1.f + (float)(p & 63) * (2.f / 63.f))
                             : (-1.f + (float)(p >> 6) * (2.f / 63.f));
    float s, c;
    __sincosf(coord * omega, &s, &c);
    __nv_bfloat16 bv = __float2bfloat16((quad & 1) ? c : s);
    g_augT[(size_t)p * KAUG + 257 + q] = bv;
    g_augT[((size_t)NPIX + p) * KAUG + 257 + q] = bv;
}

// ---------------- launch 3: x transpose + weight conversion fused ----------
// blocks [0,2048): transpose ; [2048, 2048+2112): weights (1536*352 elems)
__global__ void __launch_bounds__(256) builders(
    const float* __restrict__ x, const float* __restrict__ wq,
    const float* __restrict__ wkv, const float* __restrict__ w_hape,
    const float* __restrict__ b_hape, const float* __restrict__ wout) {
    if (blockIdx.x < 2048) {
        __shared__ float t[32][33];
        int u = blockIdx.x;
        int b = u >> 10, by = (u & 1023) >> 7, bx = u & 127;
        int pb = bx << 5, cb = by << 5;
        int tx = threadIdx.x & 31, tg = threadIdx.x >> 5;
#pragma unroll
        for (int r = 0; r < 4; ++r)
            t[tg + r * 8][tx] = x[(((size_t)b * 256 + cb + tg + r * 8) << 12) + pb + tx];
        __syncthreads();
#pragma unroll
        for (int r = 0; r < 4; ++r)
            g_augT[((size_t)((b << 12) + pb + tg + r * 8)) * KAUG + cb + tx] =
                __float2bfloat16(t[tx][tg + r * 8]);
    } else {
        int idx = (blockIdx.x - 2048) * 256 + threadIdx.x;
        if (idx < 256 * 512) g_woutb[idx] = __float2bfloat16(wout[idx]);
        if (idx >= 1536 * KAUG) return;
        int r = idx / KAUG, c = idx - r * KAUG;
        float v = 0.f;
        if (r < 512) {
            if (c < 256) v = wq[(size_t)r * 256 + c] * (0.125f * 1.44269504088896f);
        } else {
            int rr = r - 512;
            if (c < 257) v = wkv[(size_t)rr * 257 + c];
            else if (c < 324 && r < 1024) v = w_hape[(size_t)(r - 512) * 67 + (c - 257)];
        }
        g_Wb[idx] = __float2bfloat16(v);
        if (idx < 1536) g_biasC[idx] = (idx >= 512 && idx < 1024) ? b_hape[idx - 512] : 0.f;
    }
}

// ---------------- bf16 mma GEMM (Cᵀ form) — k=32 stages, 3-stage ring ------
// Tile smem: [stage][128 rows][40 pitch] bf16 per operand (A then B), dynamic.
template <int MODE>
__global__ void __launch_bounds__(256) mma_gemm(
    const __nv_bfloat16* __restrict__ A, const __nv_bfloat16* __restrict__ Bw,
    const float* __restrict__ bias, int K,
    __nv_bfloat16* __restrict__ qkv_out,
    float* __restrict__ out, const float* __restrict__ xres, const float* __restrict__ alpha) {
    extern __shared__ __nv_bfloat16 gsm[];
    const int tid = threadIdx.x, lane = tid & 31, wid = tid >> 5;
    const int wp = wid & 3, wm = wid >> 2;
    const int p0 = blockIdx.x << 7, m0 = blockIdx.y << 7, b = blockIdx.z;
    const __nv_bfloat16* Ab = A + ((size_t)b * NPIX + p0) * K;
    const __nv_bfloat16* Bb = Bw + (size_t)m0 * K;
    uint32_t base = (uint32_t)__cvta_generic_to_shared(gsm);
    uint32_t as_[3] = {base, base + 10240, base + 20480};
    uint32_t bs_[3] = {base + 30720, base + 40960, base + 51200};
    float acc[2][8][4];
#pragma unroll
    for (int i = 0; i < 2; ++i)
#pragma unroll
        for (int j = 0; j < 8; ++j)
#pragma unroll
            for (int r = 0; r < 4; ++r) acc[i][j][r] = 0.f;
    const int nst = K >> 5;   // 32-wide stages
    const int r0_ = tid >> 2, c0_ = tid & 3;   // 128 rows x 4 8-elem chunks, x2 iters
#define ISSUE(s, buf)                                                          \
    {                                                                          \
        cp16(as_[buf] + (uint32_t)(r0_ * 40 + c0_ * 8) * 2,                    \
             Ab + (size_t)r0_ * K + (s) * 32 + c0_ * 8);                       \
        cp16(as_[buf] + (uint32_t)((r0_ + 64) * 40 + c0_ * 8) * 2,             \
             Ab + (size_t)(r0_ + 64) * K + (s) * 32 + c0_ * 8);                \
        cp16(bs_[buf] + (uint32_t)(r0_ * 40 + c0_ * 8) * 2,                    \
             Bb + (size_t)r0_ * K + (s) * 32 + c0_ * 8);                       \
        cp16(bs_[buf] + (uint32_t)((r0_ + 64) * 40 + c0_ * 8) * 2,             \
             Bb + (size_t)(r0_ + 64) * K + (s) * 32 + c0_ * 8);                \
        CP_COMMIT;                                                             \
    }
    ISSUE(0, 0);
    ISSUE(1, 1);
    cp_wait<1>();
    __syncthreads();
    const uint32_t a_off = (uint32_t)(((wp * 32 + (lane & 15)) * 40 + ((lane >> 4) << 3)) * 2);
    const uint32_t b_off = (uint32_t)(((wm * 64 + (lane & 7) + ((lane >> 4) << 3)) * 40 +
                                      (((lane >> 3) & 1) << 3)) * 2);
    for (int s = 0; s < nst; ++s) {
        const int buf = s - (s / 3) * 3;
#pragma unroll
        for (int kk = 0; kk < 2; ++kk) {
            uint32_t af[2][4];
#pragma unroll
            for (int i = 0; i < 2; ++i)
                ldsm_x4(af[i], as_[buf] + a_off + (uint32_t)(i * 16 * 80 + kk * 32));
#pragma unroll
            for (int j = 0; j < 4; ++j) {
                uint32_t bf[4];
                ldsm_x4(bf, bs_[buf] + b_off + (uint32_t)(j * 16 * 80 + kk * 32));
#pragma unroll
                for (int i = 0; i < 2; ++i) {
                    mma16816(acc[i][2 * j], af[i][0], af[i][1], af[i][2], af[i][3], bf[0], bf[1]);
                    mma16816(acc[i][2 * j + 1], af[i][0], af[i][1], af[i][2], af[i][3], bf[2], bf[3]);
                }
            }
        }
        if (s + 2 < nst) {
            int nb = (s + 2) - ((s + 2) / 3) * 3;
            ISSUE(s + 2, nb);
            cp_wait<1>();
        } else {
            cp_wait<0>();
        }
        __syncthreads();
    }
#undef ISSUE
#pragma unroll
    for (int i = 0; i < 2; ++i) {
        int pr = p0 + wp * 32 + i * 16 + (lane >> 2);
        if (MODE == 0) {
            uint32_t* qo = (uint32_t*)qkv_out;
#pragma unroll
            for (int j = 0; j < 8; ++j) {
                int m = m0 + wm * 64 + j * 8 + (lane & 3) * 2;
                int part = m >> 9, hh = (m >> 6) & 7, d = m & 63;
                size_t base2 = ((size_t)(b * 3 + part) * 8 + hh) * NPIX;
                float b0f = bias[m], b1f = bias[m + 1];
                qo[((base2 + pr) * 64 + d) >> 1] = pack_bf16(acc[i][j][0] + b0f, acc[i][j][1] + b1f);
                qo[((base2 + pr + 8) * 64 + d) >> 1] = pack_bf16(acc[i][j][2] + b0f, acc[i][j][3] + b1f);
            }
        } else {
            float al0 = alpha[b * NPIX + pr], al1 = alpha[b * NPIX + pr + 8];
#pragma unroll
            for (int j = 0; j < 8; ++j) {
                int c = m0 + wm * 64 + j * 8 + (lane & 3) * 2;
                float b0f = bias[c], b1f = bias[c + 1];
                size_t i0 = ((size_t)b * 256 + c) * NPIX + pr;
                out[i0] = xres[i0] + (acc[i][j][0] + b0f) * al0;
                out[i0 + NPIX] = xres[i0 + NPIX] + (acc[i][j][1] + b1f) * al0;
                out[i0 + 8] = xres[i0 + 8] + (acc[i][j][2] + b0f) * al1;
                out[i0 + NPIX + 8] = xres[i0 + NPIX + 8] + (acc[i][j][3] + b1f) * al1;
            }
        }
    }
}

// ---------------- flash attention: unchanged from R10 (best) ----------------
template <int ROWS>
__device__ __forceinline__ void tile_load(uint32_t smem_base, const __nv_bfloat16* g, int tid) {
#pragma unroll
    for (int i = 0; i < ROWS / 32; ++i) {
        int c = tid + i * 256;
        int row = c >> 3, off = c & 7;
        cp16(smem_base + (uint32_t)(row * 144 + off * 16), g + row * 64 + off * 8);
    }
}

__global__ void __launch_bounds__(256, 2) attn_kernel(const __nv_bfloat16* __restrict__ qkv,
                                                      __nv_bfloat16* __restrict__ o_out) {
    extern __shared__ __nv_bfloat16 smem[];
    uint32_t qs = (uint32_t)__cvta_generic_to_shared(smem);
    uint32_t ks[3] = {qs + 128 * 144, qs + 128 * 144 + 9216, qs + 128 * 144 + 2 * 9216};
    uint32_t vs[3] = {qs + 128 * 144 + 3 * 9216, qs + 128 * 144 + 4 * 9216,
                      qs + 128 * 144 + 5 * 9216};

    const int tid = threadIdx.x, lane = tid & 31, wid = tid >> 5;
    const int bh = blockIdx.y;
    const int b = bh >> 3, h = bh & 7;
    const int q0 = blockIdx.x << 7;
    const __nv_bfloat16* Qg = qkv + ((size_t)(b * 24 + h) * NPIX + q0) * 64;
    const __nv_bfloat16* Kg = qkv + ((size_t)(b * 24 + 8 + h) * NPIX) * 64;
    const __nv_bfloat16* Vg = qkv + ((size_t)(b * 24 + 16 + h) * NPIX) * 64;

    tile_load<128>(qs, Qg, tid);
    tile_load<64>(ks[0], Kg, tid);
    tile_load<64>(vs[0], Vg, tid);
    CP_COMMIT;
    tile_load<64>(ks[1], Kg + 4096, tid);
    tile_load<64>(vs[1], Vg + 4096, tid);
    CP_COMMIT;
    cp_wait<1>();
    __syncthreads();

    uint32_t qf[4][4];
    {
        uint32_t qa = qs + (uint32_t)(((wid * 16 + (lane & 15)) * 72 + ((lane >> 4) << 3)) * 2);
#pragma unroll
        for (int kk = 0; kk < 4; ++kk) ldsm_x4(qf[kk], qa + kk * 32);
    }

    float l0 = 0.f, l1 = 0.f;
    float accO[8][4];
#pragma unroll
    for (int j = 0; j < 8; ++j)
#pragma unroll
        for (int r = 0; r < 4; ++r) accO[j][r] = 0.f;

    const uint32_t kb_off = (uint32_t)((((lane & 7) + ((lane >> 4) << 3)) * 72 +
                                        (((lane >> 3) & 1) << 3)) * 2);
    const uint32_t vb_off = (uint32_t)(((lane & 15) * 72 + ((lane >> 4) << 3)) * 2);

    for (int jt = 0; jt < 64; ++jt) {
        const int buf = jt - (jt / 3) * 3;
        float S[8][4];
#pragma unroll
        for (int j = 0; j < 8; ++j)
#pragma unroll
            for (int r = 0; r < 4; ++r) S[j][r] = 0.f;
#pragma unroll
        for (int kk = 0; kk < 4; ++kk) {
#pragma unroll
            for (int jj = 0; jj < 4; ++jj) {
                uint32_t bf[4];
                ldsm_x4(bf, ks[buf] + kb_off + (uint32_t)(jj * 16 * 144 + kk * 32));
                mma16816(S[2 * jj], qf[kk][0], qf[kk][1], qf[kk][2], qf[kk][3], bf[0], bf[1]);
                mma16816(S[2 * jj + 1], qf[kk][0], qf[kk][1], qf[kk][2], qf[kk][3], bf[2], bf[3]);
            }
        }
        float r0 = 0.f, r1 = 0.f;
        uint32_t pp[8][2];
#pragma unroll
        for (int j = 0; j < 8; ++j) {
            float e0 = ex2(S[j][0]), e1 = ex2(S[j][1]);
            float e2 = ex2(S[j][2]), e3 = ex2(S[j][3]);
            r0 += e0 + e1; r1 += e2 + e3;
            pp[j][0] = pack_bf16(e0, e1);
            pp[j][1] = pack_bf16(e2, e3);
        }
        r0 += __shfl_xor_sync(~0u, r0, 1);
        r0 += __shfl_xor_sync(~0u, r0, 2);
        r1 += __shfl_xor_sync(~0u, r1, 1);
        r1 += __shfl_xor_sync(~0u, r1, 2);
        l0 += r0; l1 += r1;
#pragma unroll
        for (int kk = 0; kk < 4; ++kk) {
            uint32_t a0 = pp[2 * kk][0], a1 = pp[2 * kk][1];
            uint32_t a2 = pp[2 * kk + 1][0], a3 = pp[2 * kk + 1][1];
#pragma unroll
            for (int dp = 0; dp < 4; ++dp) {
                uint32_t bf[4];
                ldsm_x4t(bf, vs[buf] + vb_off + (uint32_t)(kk * 16 * 144 + dp * 32));
                mma16816(accO[2 * dp], a0, a1, a2, a3, bf[0], bf[1]);
                mma16816(accO[2 * dp + 1], a0, a1, a2, a3, bf[2], bf[3]);
            }
        }
        if (jt + 2 < 64) {
            int nb = (jt + 2) - ((jt + 2) / 3) * 3;
            tile_load<64>(ks[nb], Kg + (size_t)(jt + 2) * 4096, tid);
            tile_load<64>(vs[nb], Vg + (size_t)(jt + 2) * 4096, tid);
            CP_COMMIT;
            cp_wait<1>();
        } else {
            cp_wait<0>();
        }
        __syncthreads();
    }

    float inv0 = 1.f / l0, inv1 = 1.f / l1;
    int qr = q0 + wid * 16 + (lane >> 2);
    uint32_t* outp = (uint32_t*)o_out;
#pragma unroll
    for (int j = 0; j < 8; ++j) {
        int dcol = h * 64 + j * 8 + (lane & 3) * 2;
        outp[(((size_t)b * NPIX + qr) * 512 + dcol) >> 1] =
            pack_bf16(accO[j][0] * inv0, accO[j][1] * inv0);
        outp[(((size_t)b * NPIX + qr + 8) * 512 + dcol) >> 1] =
            pack_bf16(accO[j][2] * inv1, accO[j][3] * inv1);
    }
}

// ---------------------------------------------------------------------------
extern "C" void kernel_launch(void* const* d_in, const int* in_sizes, int n_in,
                              void* d_out, int out_size) {
    const float* x       = (const float*)d_in[0];
    const float* dsm     = (const float*)d_in[1];
    const float* wq      = (const float*)d_in[2];
    const float* wkv     = (const float*)d_in[3];
    const float* wout    = (const float*)d_in[4];
    const float* bout    = (const float*)d_in[5];
    const float* w_hape  = (const float*)d_in[6];
    const float* b_hape  = (const float*)d_in[7];
    const float* w_alpha = (const float*)d_in[8];
    const float* b_alpha = (const float*)d_in[9];
    float* out = (float*)d_out;

    __nv_bfloat16 *pWb, *pWoutb, *pAugT, *pQkv, *pOb;
    float *pBias, *pAlpha;
    cudaGetSymbolAddress((void**)&pWb, g_Wb);
    cudaGetSymbolAddress((void**)&pWoutb, g_woutb);
    cudaGetSymbolAddress((void**)&pAugT, g_augT);
    cudaGetSymbolAddress((void**)&pQkv, g_qkvb);
    cudaGetSymbolAddress((void**)&pOb, g_ob);
    cudaGetSymbolAddress((void**)&pBias, g_biasC);
    cudaGetSymbolAddress((void**)&pAlpha, g_alpha);

    preprocess_kernel<<<2, 1024>>>(dsm, w_alpha, b_alpha);
    pe_kernel<<<1024, 256>>>();
    builders<<<2048 + (1536 * KAUG + 255) / 256, 256>>>(x, wq, wkv, w_hape, b_hape, wout);

    const int gemm_smem = 61440;  // 3 stages x (A 10240B + B 10240B)
    cudaFuncSetAttribute(mma_gemm<0>, cudaFuncAttributeMaxDynamicSharedMemorySize, gemm_smem);
    cudaFuncSetAttribute(mma_gemm<1>, cudaFuncAttributeMaxDynamicSharedMemorySize, gemm_smem);

    mma_gemm<0><<<dim3(32, 12, 2), 256, gemm_smem>>>(pAugT, pWb, pBias, KAUG, pQkv,
                                                     nullptr, nullptr, nullptr);

    const int attn_smem = (128 * 72 + 6 * 64 * 72) * 2;  // 73728 B
    cudaFuncSetAttribute(attn_kernel, cudaFuncAttributeMaxDynamicSharedMemorySize, attn_smem);
    attn_kernel<<<dim3(32, 16), 256, attn_smem>>>(pQkv, pOb);

    mma_gemm<1><<<dim3(32, 2, 2), 256, gemm_smem>>>(pOb, pWoutb, bout, 512, nullptr,
                                                    out, x, pAlpha);
}